// round 1
// baseline (speedup 1.0000x reference)
#include <cuda_runtime.h>
#include <math.h>

#define D 128
#define GMAX 4096
#define NMAX 500000

// ---- scratch (static device globals; no allocation allowed) ----
__device__ float g_h[GMAX * D];            // hidden state h (== q)
__device__ float g_c[GMAX * D];            // cell state
__device__ float g_r[GMAX * D];            // attention readout r
__device__ float g_gates[GMAX * 4 * D];    // pre-activation gates [G,512]
__device__ float g_e[NMAX];                // per-row logits / exp values
__device__ float g_Wc[4 * D * 2 * D];      // combined weight [512][256]
__device__ float g_bias[4 * D];            // b_ih + b_hh
__device__ int   g_segstart[GMAX + 1];     // segment boundaries (index is sorted)

__device__ __forceinline__ float sigf(float v) {
    return 1.0f / (1.0f + __expf(-v));
}

// ---------------------------------------------------------------------------
// prep: combined weights, bias, segment boundaries (handles int32/int64 index)
// ---------------------------------------------------------------------------
__global__ void prep_kernel(const float* __restrict__ W_ih,
                            const float* __restrict__ W_hh,
                            const float* __restrict__ b_ih,
                            const float* __restrict__ b_hh,
                            const void* __restrict__ index_raw,
                            int N, int G) {
    int tid = blockIdx.x * blockDim.x + threadIdx.x;

    // Wc[j][k] = W_ih[j][k] + (k<D ? W_hh[j][k] : 0)   (since input = [h, r], q==h)
    const int total_w = 4 * D * 2 * D;
    if (tid < total_w) {
        int j = tid / (2 * D), k = tid % (2 * D);
        float v = W_ih[(size_t)j * 2 * D + k];
        if (k < D) v += W_hh[(size_t)j * D + k];
        g_Wc[tid] = v;
    }
    if (tid < 4 * D) g_bias[tid] = b_ih[tid] + b_hh[tid];

    if (tid <= G) {
        // detect int64 vs int32: for sorted int64 values in [0, 2^31), odd
        // 32-bit words are zero; for int32 they hold large sorted index values.
        const int* p32 = (const int*)index_raw;
        int j1 = N - 1;
        if ((j1 & 1) == 0) j1--;       // largest odd position < N
        int is64 = 1;
        if (j1 >= 5) {
            if (p32[j1] != 0 || p32[j1 - 2] != 0 || p32[j1 - 4] != 0) is64 = 0;
        }
        const long long* p64 = (const long long*)index_raw;
        // lower_bound: first i with index[i] >= tid
        int lo = 0, hi = N;
        while (lo < hi) {
            int mid = (lo + hi) >> 1;
            long long v = is64 ? p64[mid] : (long long)p32[mid];
            if (v < (long long)tid) lo = mid + 1; else hi = mid;
        }
        g_segstart[tid] = lo;
    }
}

// ---------------------------------------------------------------------------
// step 1 special case: q_star=0, h=0, c=0  ->  gates = bias (same for all rows)
// ---------------------------------------------------------------------------
__global__ void init_state_kernel(int G) {
    int tid = blockIdx.x * blockDim.x + threadIdx.x;
    if (tid >= G * D) return;
    int d = tid % D;
    float bi = g_bias[d], bg = g_bias[2 * D + d], bo = g_bias[3 * D + d];
    float c = sigf(bi) * tanhf(bg);          // sig(f)*c0 term is 0
    float h = sigf(bo) * tanhf(c);
    g_c[tid] = c;
    g_h[tid] = h;
}

// ---------------------------------------------------------------------------
// per-segment fused attention: e = x.q, segment softmax, r = sum a*x
// one block per segment (index sorted => contiguous rows). Second x read
// hits L2 (segment ~62KB just streamed by this block).
// ---------------------------------------------------------------------------
__global__ void __launch_bounds__(256) segment_kernel(const float* __restrict__ x) {
    int g = blockIdx.x;
    int start = g_segstart[g];
    int end   = g_segstart[g + 1];

    __shared__ float qs[D];
    __shared__ float red[8];
    __shared__ float rsm[8][D];

    int tid = threadIdx.x, warp = tid >> 5, lane = tid & 31;

    if (tid < D) qs[tid] = g_h[(size_t)g * D + tid];
    __syncthreads();
    float4 myq = ((const float4*)qs)[lane];

    // phase 1: logits + segment max (one row per warp)
    float lmax = -3.402823e38f;
    for (int row = start + warp; row < end; row += 8) {
        float4 v = ((const float4*)(x + (size_t)row * D))[lane];
        float dv = v.x * myq.x + v.y * myq.y + v.z * myq.z + v.w * myq.w;
        #pragma unroll
        for (int o = 16; o > 0; o >>= 1) dv += __shfl_xor_sync(0xffffffffu, dv, o);
        if (lane == 0) g_e[row] = dv;
        lmax = fmaxf(lmax, dv);
    }
    if (lane == 0) red[warp] = lmax;
    __syncthreads();
    if (tid == 0) {
        float mm = red[0];
        #pragma unroll
        for (int i = 1; i < 8; i++) mm = fmaxf(mm, red[i]);
        red[0] = mm;
    }
    __syncthreads();
    float m = red[0];

    // phase 2: exp + segment sum (over e only, no x traffic)
    float lsum = 0.0f;
    for (int i = start + tid; i < end; i += 256) {
        float ex = __expf(g_e[i] - m);
        g_e[i] = ex;
        lsum += ex;
    }
    #pragma unroll
    for (int o = 16; o > 0; o >>= 1) lsum += __shfl_xor_sync(0xffffffffu, lsum, o);
    __syncthreads();                    // m consumed; g_e writes visible after next sync
    if (lane == 0) red[warp] = lsum;
    __syncthreads();
    if (tid == 0) {
        float s = 0.0f;
        #pragma unroll
        for (int i = 0; i < 8; i++) s += red[i];
        red[0] = 1.0f / fmaxf(s, 1e-16f);
    }
    __syncthreads();
    float inv = red[0];

    // phase 3: r = sum a * x   (x rows re-read: L2/L1 hot)
    float4 acc = make_float4(0.f, 0.f, 0.f, 0.f);
    for (int row = start + warp; row < end; row += 8) {
        float w = g_e[row] * inv;
        float4 v = ((const float4*)(x + (size_t)row * D))[lane];
        acc.x += w * v.x; acc.y += w * v.y; acc.z += w * v.z; acc.w += w * v.w;
    }
    ((float4*)rsm[warp])[lane] = acc;
    __syncthreads();
    if (tid < D) {
        float s = 0.0f;
        #pragma unroll
        for (int w = 0; w < 8; w++) s += rsm[w][tid];
        g_r[(size_t)g * D + tid] = s;
    }
}

// ---------------------------------------------------------------------------
// gates = [h | r] @ Wc^T   (M=G, N=512, K=256)  fp32 SIMT tiled GEMM
// BM=64, BN=64, BK=16, 256 threads, 4x4 register tile per thread
// ---------------------------------------------------------------------------
__global__ void __launch_bounds__(256) gates_gemm(int G) {
    __shared__ float As[16][65];
    __shared__ float Bs[16][65];

    int bm = blockIdx.x * 64;
    int bn = blockIdx.y * 64;
    int tid = threadIdx.x;

    int lm = tid >> 2;           // 0..63 (row within tile for loads)
    int lk = (tid & 3) * 4;      // 0,4,8,12 (k within tile for loads)
    int tx = tid & 15;           // output col group
    int ty = tid >> 4;           // output row group

    float acc[4][4];
    #pragma unroll
    for (int i = 0; i < 4; i++)
        #pragma unroll
        for (int j = 0; j < 4; j++) acc[i][j] = 0.0f;

    for (int k0 = 0; k0 < 256; k0 += 16) {
        int kg = k0 + lk;
        int row = bm + lm;
        const float* asrc = (kg < D) ? (g_h + (size_t)row * D + kg)
                                     : (g_r + (size_t)row * D + (kg - D));
        float4 a = *(const float4*)asrc;
        As[lk + 0][lm] = a.x; As[lk + 1][lm] = a.y;
        As[lk + 2][lm] = a.z; As[lk + 3][lm] = a.w;

        float4 b = *(const float4*)(g_Wc + (size_t)(bn + lm) * 256 + kg);
        Bs[lk + 0][lm] = b.x; Bs[lk + 1][lm] = b.y;
        Bs[lk + 2][lm] = b.z; Bs[lk + 3][lm] = b.w;
        __syncthreads();

        #pragma unroll
        for (int kk = 0; kk < 16; kk++) {
            float av[4], bv[4];
            #pragma unroll
            for (int i = 0; i < 4; i++) av[i] = As[kk][ty * 4 + i];
            #pragma unroll
            for (int j = 0; j < 4; j++) bv[j] = Bs[kk][tx * 4 + j];
            #pragma unroll
            for (int i = 0; i < 4; i++)
                #pragma unroll
                for (int j = 0; j < 4; j++)
                    acc[i][j] = fmaf(av[i], bv[j], acc[i][j]);
        }
        __syncthreads();
    }

    #pragma unroll
    for (int i = 0; i < 4; i++) {
        int row = bm + ty * 4 + i;
        #pragma unroll
        for (int j = 0; j < 4; j++) {
            g_gates[(size_t)row * (4 * D) + bn + tx * 4 + j] = acc[i][j];
        }
    }
}

// ---------------------------------------------------------------------------
// LSTM elementwise update: c,h <- gate activations
// ---------------------------------------------------------------------------
__global__ void lstm_update(int G) {
    int tid = blockIdx.x * blockDim.x + threadIdx.x;
    if (tid >= G * D) return;
    int row = tid / D, d = tid % D;
    const float* gr = g_gates + (size_t)row * 4 * D;
    float gi = gr[d]         + g_bias[d];
    float gf = gr[D + d]     + g_bias[D + d];
    float gg = gr[2 * D + d] + g_bias[2 * D + d];
    float go = gr[3 * D + d] + g_bias[3 * D + d];
    float c = sigf(gf) * g_c[tid] + sigf(gi) * tanhf(gg);
    float h = sigf(go) * tanhf(c);
    g_c[tid] = c;
    g_h[tid] = h;
}

// ---------------------------------------------------------------------------
// final output: q_star = [h | r]
// ---------------------------------------------------------------------------
__global__ void assemble_kernel(float* __restrict__ out, int G) {
    int tid = blockIdx.x * blockDim.x + threadIdx.x;
    if (tid >= G * 2 * D) return;
    int row = tid / (2 * D), d = tid % (2 * D);
    out[tid] = (d < D) ? g_h[(size_t)row * D + d]
                       : g_r[(size_t)row * D + (d - D)];
}

// ---------------------------------------------------------------------------
extern "C" void kernel_launch(void* const* d_in, const int* in_sizes, int n_in,
                              void* d_out, int out_size) {
    const float* x    = (const float*)d_in[0];
    const float* W_ih = (const float*)d_in[1];
    const float* W_hh = (const float*)d_in[2];
    const float* b_ih = (const float*)d_in[3];
    const float* b_hh = (const float*)d_in[4];
    const void*  idx  = d_in[5];
    int N = in_sizes[5];
    int G = out_size / (2 * D);      // 4096
    float* out = (float*)d_out;

    int prep_total = 4 * D * 2 * D;  // 131072 >= G+1
    prep_kernel<<<(prep_total + 255) / 256, 256>>>(W_ih, W_hh, b_ih, b_hh, idx, N, G);
    init_state_kernel<<<(G * D + 255) / 256, 256>>>(G);
    segment_kernel<<<G, 256>>>(x);

    dim3 ggrid(G / 64, (4 * D) / 64);
    for (int s = 1; s < 3; s++) {
        gates_gemm<<<ggrid, 256>>>(G);
        lstm_update<<<(G * D + 255) / 256, 256>>>(G);
        segment_kernel<<<G, 256>>>(x);
    }
    assemble_kernel<<<(G * 2 * D + 255) / 256, 256>>>(out, G);
}

// round 2
// speedup vs baseline: 1.2012x; 1.2012x over previous
#include <cuda_runtime.h>
#include <cuda_bf16.h>
#include <math.h>

#define D 128
#define GMAX 4096
#define NMAX 500000

// ---- scratch (static device globals; no allocation allowed) ----
__device__ float g_h[GMAX * D];            // hidden state h (== q), fp32
__device__ float g_c[GMAX * D];            // cell state
__device__ float g_r[GMAX * D];            // attention readout r, fp32
__device__ float g_gates[GMAX * 4 * D];    // pre-activation gates [G,512]
__device__ float g_e[NMAX];                // per-row logits / exp values
__device__ float g_bias[4 * D];            // b_ih + b_hh
__device__ int   g_segstart[GMAX + 1];     // segment boundaries (index sorted)

// bf16 split operands for tensor-core GEMM:
// A panel [G][512]: cols 0-127 hi(h), 128-255 hi(r), 256-383 lo(h), 384-511 lo(r)
__device__ __nv_bfloat16 g_A[GMAX * 512];
// B panel [512 n][768 k]: k<256 -> Bh[k]; 256..511 -> Bl[k-256]; 512..767 -> Bh[k-512]
__device__ __nv_bfloat16 g_Wb[512 * 768];

__device__ __forceinline__ float sigf(float v) {
    return 1.0f / (1.0f + __expf(-v));
}

// ---------------------------------------------------------------------------
// prep: split weights (bf16 hi/lo panel), bias, segment boundaries
// ---------------------------------------------------------------------------
__global__ void prep_kernel(const float* __restrict__ W_ih,
                            const float* __restrict__ W_hh,
                            const float* __restrict__ b_ih,
                            const float* __restrict__ b_hh,
                            const void* __restrict__ index_raw,
                            int N, int G) {
    int tid = blockIdx.x * blockDim.x + threadIdx.x;

    // Wc[n][k] = W_ih[n][k] + (k<D ? W_hh[n][k] : 0)  (input = [h, r], q==h)
    if (tid < 512 * 768) {
        int n = tid / 768, k = tid % 768;
        int kk = (k < 256) ? k : ((k < 512) ? k - 256 : k - 512);
        float w = W_ih[(size_t)n * 256 + kk];
        if (kk < D) w += W_hh[(size_t)n * D + kk];
        __nv_bfloat16 hi = __float2bfloat16(w);
        if (k >= 256 && k < 512) {
            g_Wb[tid] = __float2bfloat16(w - __bfloat162float(hi));  // lo part
        } else {
            g_Wb[tid] = hi;
        }
    }
    if (tid < 4 * D) g_bias[tid] = b_ih[tid] + b_hh[tid];

    if (tid <= G) {
        // detect int64 vs int32 index (sorted, values < 2^31)
        const int* p32 = (const int*)index_raw;
        int j1 = N - 1;
        if ((j1 & 1) == 0) j1--;
        int is64 = 1;
        if (j1 >= 5) {
            if (p32[j1] != 0 || p32[j1 - 2] != 0 || p32[j1 - 4] != 0) is64 = 0;
        }
        const long long* p64 = (const long long*)index_raw;
        int lo = 0, hi = N;
        while (lo < hi) {
            int mid = (lo + hi) >> 1;
            long long v = is64 ? p64[mid] : (long long)p32[mid];
            if (v < (long long)tid) lo = mid + 1; else hi = mid;
        }
        g_segstart[tid] = lo;
    }
}

// ---------------------------------------------------------------------------
// step 1 special: q_star=0, h=0, c=0 -> gates = bias (identical rows)
// ---------------------------------------------------------------------------
__global__ void init_state_kernel(int G) {
    int tid = blockIdx.x * blockDim.x + threadIdx.x;
    if (tid >= G * D) return;
    int row = tid / D, d = tid % D;
    float bi = g_bias[d], bg = g_bias[2 * D + d], bo = g_bias[3 * D + d];
    float c = sigf(bi) * tanhf(bg);
    float h = sigf(bo) * tanhf(c);
    g_c[tid] = c;
    g_h[tid] = h;
    __nv_bfloat16 hh = __float2bfloat16(h);
    g_A[(size_t)row * 512 + d] = hh;
    g_A[(size_t)row * 512 + 256 + d] = __float2bfloat16(h - __bfloat162float(hh));
}

// ---------------------------------------------------------------------------
// per-segment fused attention: e = x.q, segment softmax, r = sum a*x
// ---------------------------------------------------------------------------
__global__ void __launch_bounds__(256) segment_kernel(const float* __restrict__ x) {
    int g = blockIdx.x;
    int start = g_segstart[g];
    int end   = g_segstart[g + 1];

    __shared__ float qs[D];
    __shared__ float red[8];
    __shared__ float rsm[8][D];

    int tid = threadIdx.x, warp = tid >> 5, lane = tid & 31;

    if (tid < D) qs[tid] = g_h[(size_t)g * D + tid];
    __syncthreads();
    float4 myq = ((const float4*)qs)[lane];

    // phase 1: logits + segment max (one row per warp)
    float lmax = -3.402823e38f;
    for (int row = start + warp; row < end; row += 8) {
        float4 v = ((const float4*)(x + (size_t)row * D))[lane];
        float dv = v.x * myq.x + v.y * myq.y + v.z * myq.z + v.w * myq.w;
        #pragma unroll
        for (int o = 16; o > 0; o >>= 1) dv += __shfl_xor_sync(0xffffffffu, dv, o);
        if (lane == 0) g_e[row] = dv;
        lmax = fmaxf(lmax, dv);
    }
    if (lane == 0) red[warp] = lmax;
    __syncthreads();
    if (tid == 0) {
        float mm = red[0];
        #pragma unroll
        for (int i = 1; i < 8; i++) mm = fmaxf(mm, red[i]);
        red[0] = mm;
    }
    __syncthreads();
    float m = red[0];

    // phase 2: exp + segment sum
    float lsum = 0.0f;
    for (int i = start + tid; i < end; i += 256) {
        float ex = __expf(g_e[i] - m);
        g_e[i] = ex;
        lsum += ex;
    }
    #pragma unroll
    for (int o = 16; o > 0; o >>= 1) lsum += __shfl_xor_sync(0xffffffffu, lsum, o);
    __syncthreads();
    if (lane == 0) red[warp] = lsum;
    __syncthreads();
    if (tid == 0) {
        float s = 0.0f;
        #pragma unroll
        for (int i = 0; i < 8; i++) s += red[i];
        red[0] = 1.0f / fmaxf(s, 1e-16f);
    }
    __syncthreads();
    float inv = red[0];

    // phase 3: r = sum a * x (x rows hot in L2)
    float4 acc = make_float4(0.f, 0.f, 0.f, 0.f);
    for (int row = start + warp; row < end; row += 8) {
        float w = g_e[row] * inv;
        float4 v = ((const float4*)(x + (size_t)row * D))[lane];
        acc.x += w * v.x; acc.y += w * v.y; acc.z += w * v.z; acc.w += w * v.w;
    }
    ((float4*)rsm[warp])[lane] = acc;
    __syncthreads();
    if (tid < D) {
        float s = 0.0f;
        #pragma unroll
        for (int w = 0; w < 8; w++) s += rsm[w][tid];
        g_r[(size_t)g * D + tid] = s;
        __nv_bfloat16 hh = __float2bfloat16(s);
        g_A[(size_t)g * 512 + 128 + tid] = hh;
        g_A[(size_t)g * 512 + 384 + tid] = __float2bfloat16(s - __bfloat162float(hh));
    }
}

// ---------------------------------------------------------------------------
// gates = A' @ B'^T via mma.sync m16n8k16 bf16 (hi/lo split, K=768)
// block tile 128x64, 8 warps (4x2), warp tile 32x32
// ---------------------------------------------------------------------------
#define ASTRIDE 72
__global__ void __launch_bounds__(256) gates_gemm_mma() {
    __shared__ __nv_bfloat16 As[128 * ASTRIDE];
    __shared__ __nv_bfloat16 Bs[64 * ASTRIDE];

    int bm = blockIdx.x * 128;
    int bn = blockIdx.y * 64;
    int t = threadIdx.x, warp = t >> 5, lane = t & 31;
    int wm = (warp & 3) * 32;      // warp m offset within block
    int wn = (warp >> 2) * 32;     // warp n offset within block
    int gid = lane >> 2, tig = lane & 3;

    float acc[2][4][4];
    #pragma unroll
    for (int mi = 0; mi < 2; mi++)
        #pragma unroll
        for (int ni = 0; ni < 4; ni++)
            #pragma unroll
            for (int cc = 0; cc < 4; cc++) acc[mi][ni][cc] = 0.0f;

    for (int c = 0; c < 12; c++) {
        // A' k-chunk source base within g_A's 512 cols:
        // chunks 0-3: Ah (cols 0-255); 4-7: Ah again; 8-11: Al (cols 256-511)
        int abase = (c < 4) ? c * 64 : (c < 8 ? (c - 4) * 64 : 256 + (c - 8) * 64);
        int bbase = c * 64;

        // load A tile 128x64 (1024 uint4 total, 4 per thread)
        #pragma unroll
        for (int i = 0; i < 4; i++) {
            int idx = t + i * 256;
            int row = idx >> 3, c8 = idx & 7;
            uint4 v = *(const uint4*)(g_A + (size_t)(bm + row) * 512 + abase + c8 * 8);
            *(uint2*)(As + row * ASTRIDE + c8 * 8)     = make_uint2(v.x, v.y);
            *(uint2*)(As + row * ASTRIDE + c8 * 8 + 4) = make_uint2(v.z, v.w);
        }
        // load B tile 64x64 (512 uint4 total, 2 per thread)
        #pragma unroll
        for (int i = 0; i < 2; i++) {
            int idx = t + i * 256;
            int row = idx >> 3, c8 = idx & 7;
            uint4 v = *(const uint4*)(g_Wb + (size_t)(bn + row) * 768 + bbase + c8 * 8);
            *(uint2*)(Bs + row * ASTRIDE + c8 * 8)     = make_uint2(v.x, v.y);
            *(uint2*)(Bs + row * ASTRIDE + c8 * 8 + 4) = make_uint2(v.z, v.w);
        }
        __syncthreads();

        #pragma unroll
        for (int k0 = 0; k0 < 64; k0 += 16) {
            // B fragments for 4 n8 tiles
            unsigned b0[4], b1[4];
            #pragma unroll
            for (int ni = 0; ni < 4; ni++) {
                const __nv_bfloat16* bp = Bs + (wn + ni * 8 + gid) * ASTRIDE + k0 + tig * 2;
                b0[ni] = *(const unsigned*)bp;
                b1[ni] = *(const unsigned*)(bp + 8);
            }
            #pragma unroll
            for (int mi = 0; mi < 2; mi++) {
                const __nv_bfloat16* ap = As + (wm + mi * 16 + gid) * ASTRIDE + k0 + tig * 2;
                unsigned a0 = *(const unsigned*)ap;
                unsigned a1 = *(const unsigned*)(ap + 8 * ASTRIDE);
                unsigned a2 = *(const unsigned*)(ap + 8);
                unsigned a3 = *(const unsigned*)(ap + 8 * ASTRIDE + 8);
                #pragma unroll
                for (int ni = 0; ni < 4; ni++) {
                    asm volatile(
                        "mma.sync.aligned.m16n8k16.row.col.f32.bf16.bf16.f32 "
                        "{%0,%1,%2,%3}, {%4,%5,%6,%7}, {%8,%9}, {%0,%1,%2,%3};\n"
                        : "+f"(acc[mi][ni][0]), "+f"(acc[mi][ni][1]),
                          "+f"(acc[mi][ni][2]), "+f"(acc[mi][ni][3])
                        : "r"(a0), "r"(a1), "r"(a2), "r"(a3),
                          "r"(b0[ni]), "r"(b1[ni]));
                }
            }
        }
        __syncthreads();
    }

    // epilogue: c0,c1 -> (row, col..col+1); c2,c3 -> (row+8, col..col+1)
    #pragma unroll
    for (int mi = 0; mi < 2; mi++) {
        int row = bm + wm + mi * 16 + gid;
        #pragma unroll
        for (int ni = 0; ni < 4; ni++) {
            int col = bn + wn + ni * 8 + tig * 2;
            *(float2*)(g_gates + (size_t)row * 512 + col) =
                make_float2(acc[mi][ni][0], acc[mi][ni][1]);
            *(float2*)(g_gates + (size_t)(row + 8) * 512 + col) =
                make_float2(acc[mi][ni][2], acc[mi][ni][3]);
        }
    }
}

// ---------------------------------------------------------------------------
// LSTM elementwise update (also emits bf16 hi/lo of new h into A panel)
// ---------------------------------------------------------------------------
__global__ void lstm_update(int G) {
    int tid = blockIdx.x * blockDim.x + threadIdx.x;
    if (tid >= G * D) return;
    int row = tid / D, d = tid % D;
    const float* gr = g_gates + (size_t)row * 4 * D;
    float gi = gr[d]         + g_bias[d];
    float gf = gr[D + d]     + g_bias[D + d];
    float gg = gr[2 * D + d] + g_bias[2 * D + d];
    float go = gr[3 * D + d] + g_bias[3 * D + d];
    float c = sigf(gf) * g_c[tid] + sigf(gi) * tanhf(gg);
    float h = sigf(go) * tanhf(c);
    g_c[tid] = c;
    g_h[tid] = h;
    __nv_bfloat16 hh = __float2bfloat16(h);
    g_A[(size_t)row * 512 + d] = hh;
    g_A[(size_t)row * 512 + 256 + d] = __float2bfloat16(h - __bfloat162float(hh));
}

// ---------------------------------------------------------------------------
// final output: q_star = [h | r]
// ---------------------------------------------------------------------------
__global__ void assemble_kernel(float* __restrict__ out, int G) {
    int tid = blockIdx.x * blockDim.x + threadIdx.x;
    if (tid >= G * 2 * D) return;
    int row = tid / (2 * D), d = tid % (2 * D);
    out[tid] = (d < D) ? g_h[(size_t)row * D + d]
                       : g_r[(size_t)row * D + (d - D)];
}

// ---------------------------------------------------------------------------
extern "C" void kernel_launch(void* const* d_in, const int* in_sizes, int n_in,
                              void* d_out, int out_size) {
    const float* x    = (const float*)d_in[0];
    const float* W_ih = (const float*)d_in[1];
    const float* W_hh = (const float*)d_in[2];
    const float* b_ih = (const float*)d_in[3];
    const float* b_hh = (const float*)d_in[4];
    const void*  idx  = d_in[5];
    int N = in_sizes[5];
    int G = out_size / (2 * D);      // 4096
    float* out = (float*)d_out;

    int prep_total = 512 * 768;
    prep_kernel<<<(prep_total + 255) / 256, 256>>>(W_ih, W_hh, b_ih, b_hh, idx, N, G);
    init_state_kernel<<<(G * D + 255) / 256, 256>>>(G);
    segment_kernel<<<G, 256>>>(x);

    dim3 ggrid(G / 128, 512 / 64);
    for (int s = 1; s < 3; s++) {
        gates_gemm_mma<<<ggrid, 256>>>();
        lstm_update<<<(G * D + 255) / 256, 256>>>(G);
        segment_kernel<<<G, 256>>>(x);
    }
    assemble_kernel<<<(G * 2 * D + 255) / 256, 256>>>(out, G);
}

// round 3
// speedup vs baseline: 1.4541x; 1.2106x over previous
#include <cuda_runtime.h>
#include <cuda_bf16.h>
#include <math.h>

#define D 128
#define GMAX 4096
#define NMAX 500000

// ---- scratch (static device globals; no allocation allowed) ----
__device__ float g_h[GMAX * D];            // hidden state h (== q), fp32
__device__ float g_c[GMAX * D];            // cell state
__device__ float g_r[GMAX * D];            // attention readout r, fp32
__device__ float g_gates[GMAX * 4 * D];    // pre-activation gates [G,512]
__device__ float g_bias[4 * D];            // b_ih + b_hh
__device__ int   g_segstart[GMAX + 1];     // segment boundaries (index sorted)

// bf16 split operands for tensor-core GEMM:
// A panel [G][512]: cols 0-127 hi(h), 128-255 hi(r), 256-383 lo(h), 384-511 lo(r)
__device__ __nv_bfloat16 g_A[GMAX * 512];
// B panel [512 n][768 k]: k<256 -> Bh[k]; 256..511 -> Bl[k-256]; 512..767 -> Bh[k-512]
__device__ __nv_bfloat16 g_Wb[512 * 768];

__device__ __forceinline__ float sigf(float v) {
    return 1.0f / (1.0f + __expf(-v));
}

__device__ __forceinline__ unsigned smem_u32(const void* p) {
    return (unsigned)__cvta_generic_to_shared(p);
}
__device__ __forceinline__ void cp16(void* dst, const void* src) {
    asm volatile("cp.async.cg.shared.global [%0], [%1], 16;\n"
                 :: "r"(smem_u32(dst)), "l"(src));
}
__device__ __forceinline__ void cp_commit() {
    asm volatile("cp.async.commit_group;\n");
}
template <int N> __device__ __forceinline__ void cp_wait() {
    asm volatile("cp.async.wait_group %0;\n" :: "n"(N));
}

// ---------------------------------------------------------------------------
// prep: split weights (bf16 hi/lo panel), bias, segment boundaries
// ---------------------------------------------------------------------------
__global__ void prep_kernel(const float* __restrict__ W_ih,
                            const float* __restrict__ W_hh,
                            const float* __restrict__ b_ih,
                            const float* __restrict__ b_hh,
                            const void* __restrict__ index_raw,
                            int N, int G) {
    int tid = blockIdx.x * blockDim.x + threadIdx.x;

    if (tid < 512 * 768) {
        int n = tid / 768, k = tid % 768;
        int kk = (k < 256) ? k : ((k < 512) ? k - 256 : k - 512);
        float w = W_ih[(size_t)n * 256 + kk];
        if (kk < D) w += W_hh[(size_t)n * D + kk];
        __nv_bfloat16 hi = __float2bfloat16(w);
        if (k >= 256 && k < 512) {
            g_Wb[tid] = __float2bfloat16(w - __bfloat162float(hi));  // lo part
        } else {
            g_Wb[tid] = hi;
        }
    }
    if (tid < 4 * D) g_bias[tid] = b_ih[tid] + b_hh[tid];

    if (tid <= G) {
        // detect int64 vs int32 index (sorted, values < 2^31)
        const int* p32 = (const int*)index_raw;
        int j1 = N - 1;
        if ((j1 & 1) == 0) j1--;
        int is64 = 1;
        if (j1 >= 5) {
            if (p32[j1] != 0 || p32[j1 - 2] != 0 || p32[j1 - 4] != 0) is64 = 0;
        }
        const long long* p64 = (const long long*)index_raw;
        int lo = 0, hi = N;
        while (lo < hi) {
            int mid = (lo + hi) >> 1;
            long long v = is64 ? p64[mid] : (long long)p32[mid];
            if (v < (long long)tid) lo = mid + 1; else hi = mid;
        }
        g_segstart[tid] = lo;
    }
}

// ---------------------------------------------------------------------------
// step 1 special: q_star=0, h=0, c=0 -> gates = bias (identical rows)
// ---------------------------------------------------------------------------
__global__ void init_state_kernel(int G) {
    int tid = blockIdx.x * blockDim.x + threadIdx.x;
    if (tid >= G * D) return;
    int row = tid / D, d = tid % D;
    float bi = g_bias[d], bg = g_bias[2 * D + d], bo = g_bias[3 * D + d];
    float c = sigf(bi) * tanhf(bg);
    float h = sigf(bo) * tanhf(c);
    g_c[tid] = c;
    g_h[tid] = h;
    __nv_bfloat16 hh = __float2bfloat16(h);
    g_A[(size_t)row * 512 + d] = hh;
    g_A[(size_t)row * 512 + 256 + d] = __float2bfloat16(h - __bfloat162float(hh));
}

// ---------------------------------------------------------------------------
// fused single-pass segment attention (online softmax):
// one block per segment; warp keeps running (m, s, acc[128]) and rescales.
// ---------------------------------------------------------------------------
__global__ void __launch_bounds__(256) segment_kernel(const float* __restrict__ x) {
    int g = blockIdx.x;
    int start = g_segstart[g];
    int end   = g_segstart[g + 1];

    __shared__ float qs[D];
    __shared__ float wm[8], ws[8], wf[8];
    __shared__ float wacc[8][D];

    int tid = threadIdx.x, warp = tid >> 5, lane = tid & 31;

    if (tid < D) qs[tid] = g_h[(size_t)g * D + tid];
    __syncthreads();
    float4 myq = ((const float4*)qs)[lane];

    float m = -3.402823e38f, s = 0.0f;
    float4 acc = make_float4(0.f, 0.f, 0.f, 0.f);

    int row = start + warp;
    for (; row + 8 < end; row += 16) {
        float4 v0 = ((const float4*)(x + (size_t)row * D))[lane];
        float4 v1 = ((const float4*)(x + (size_t)(row + 8) * D))[lane];
        float d0 = v0.x * myq.x + v0.y * myq.y + v0.z * myq.z + v0.w * myq.w;
        float d1 = v1.x * myq.x + v1.y * myq.y + v1.z * myq.z + v1.w * myq.w;
        #pragma unroll
        for (int o = 16; o > 0; o >>= 1) {
            d0 += __shfl_xor_sync(0xffffffffu, d0, o);
            d1 += __shfl_xor_sync(0xffffffffu, d1, o);
        }
        // row
        float nm = fmaxf(m, d0);
        float sc = __expf(m - nm);
        float p  = __expf(d0 - nm);
        s = s * sc + p;
        acc.x = acc.x * sc + p * v0.x; acc.y = acc.y * sc + p * v0.y;
        acc.z = acc.z * sc + p * v0.z; acc.w = acc.w * sc + p * v0.w;
        m = nm;
        // row + 8
        nm = fmaxf(m, d1);
        sc = __expf(m - nm);
        p  = __expf(d1 - nm);
        s = s * sc + p;
        acc.x = acc.x * sc + p * v1.x; acc.y = acc.y * sc + p * v1.y;
        acc.z = acc.z * sc + p * v1.z; acc.w = acc.w * sc + p * v1.w;
        m = nm;
    }
    if (row < end) {
        float4 v0 = ((const float4*)(x + (size_t)row * D))[lane];
        float d0 = v0.x * myq.x + v0.y * myq.y + v0.z * myq.z + v0.w * myq.w;
        #pragma unroll
        for (int o = 16; o > 0; o >>= 1) d0 += __shfl_xor_sync(0xffffffffu, d0, o);
        float nm = fmaxf(m, d0);
        float sc = __expf(m - nm);
        float p  = __expf(d0 - nm);
        s = s * sc + p;
        acc.x = acc.x * sc + p * v0.x; acc.y = acc.y * sc + p * v0.y;
        acc.z = acc.z * sc + p * v0.z; acc.w = acc.w * sc + p * v0.w;
        m = nm;
    }

    ((float4*)wacc[warp])[lane] = acc;
    if (lane == 0) { wm[warp] = m; ws[warp] = s; }
    __syncthreads();

    if (tid == 0) {
        float M = wm[0];
        #pragma unroll
        for (int i = 1; i < 8; i++) M = fmaxf(M, wm[i]);
        float f[8], S = 0.0f;
        if (isfinite(M)) {
            #pragma unroll
            for (int i = 0; i < 8; i++) { f[i] = __expf(wm[i] - M); S += f[i] * ws[i]; }
        } else {
            #pragma unroll
            for (int i = 0; i < 8; i++) f[i] = 0.0f;
        }
        float inv = 1.0f / fmaxf(S, 1e-16f);
        #pragma unroll
        for (int i = 0; i < 8; i++) wf[i] = f[i] * inv;
    }
    __syncthreads();

    if (tid < D) {
        float r = 0.0f;
        #pragma unroll
        for (int w = 0; w < 8; w++) r += wf[w] * wacc[w][tid];
        g_r[(size_t)g * D + tid] = r;
        __nv_bfloat16 hh = __float2bfloat16(r);
        g_A[(size_t)g * 512 + 128 + tid] = hh;
        g_A[(size_t)g * 512 + 384 + tid] = __float2bfloat16(r - __bfloat162float(hh));
    }
}

// ---------------------------------------------------------------------------
// gates = A' @ B'^T via mma.sync m16n8k16 bf16, K=768 (hi/lo split)
// block tile 128x64, 8 warps, double-buffered cp.async, XOR-swizzled smem
// ---------------------------------------------------------------------------
__device__ __forceinline__ __nv_bfloat16* swaddr(__nv_bfloat16* base, int row, int k) {
    int kb = k >> 3, ko = k & 7;
    return base + row * 64 + ((kb ^ (row & 7)) << 3) + ko;
}

__global__ void __launch_bounds__(256) gates_gemm_mma() {
    __shared__ __align__(16) __nv_bfloat16 As[2][128 * 64];
    __shared__ __align__(16) __nv_bfloat16 Bs[2][64 * 64];

    int bm = blockIdx.x * 128;
    int bn = blockIdx.y * 64;
    int t = threadIdx.x, warp = t >> 5, lane = t & 31;
    int wm_ = (warp & 3) * 32;
    int wn_ = (warp >> 2) * 32;
    int gid = lane >> 2, tig = lane & 3;

    float acc[2][4][4];
    #pragma unroll
    for (int mi = 0; mi < 2; mi++)
        #pragma unroll
        for (int ni = 0; ni < 4; ni++)
            #pragma unroll
            for (int cc = 0; cc < 4; cc++) acc[mi][ni][cc] = 0.0f;

    // chunk c: A source base (within 512 cols), B base = c*64
    auto issue_load = [&](int stage, int c) {
        int abase = (c < 4) ? c * 64 : (c < 8 ? (c - 4) * 64 : 256 + (c - 8) * 64);
        int bbase = c * 64;
        #pragma unroll
        for (int i = 0; i < 4; i++) {
            int idx = t + i * 256;
            int row = idx >> 3, c8 = idx & 7;
            cp16(As[stage] + row * 64 + ((c8 ^ (row & 7)) << 3),
                 g_A + (size_t)(bm + row) * 512 + abase + c8 * 8);
        }
        #pragma unroll
        for (int i = 0; i < 2; i++) {
            int idx = t + i * 256;
            int row = idx >> 3, c8 = idx & 7;
            cp16(Bs[stage] + row * 64 + ((c8 ^ (row & 7)) << 3),
                 g_Wb + (size_t)(bn + row) * 768 + bbase + c8 * 8);
        }
        cp_commit();
    };

    issue_load(0, 0);

    for (int c = 0; c < 12; c++) {
        if (c + 1 < 12) {
            issue_load((c + 1) & 1, c + 1);
            cp_wait<1>();
        } else {
            cp_wait<0>();
        }
        __syncthreads();

        __nv_bfloat16* Ac = As[c & 1];
        __nv_bfloat16* Bc = Bs[c & 1];

        #pragma unroll
        for (int k0 = 0; k0 < 64; k0 += 16) {
            unsigned b0[4], b1[4];
            #pragma unroll
            for (int ni = 0; ni < 4; ni++) {
                int br = wn_ + ni * 8 + gid;
                b0[ni] = *(const unsigned*)swaddr(Bc, br, k0 + tig * 2);
                b1[ni] = *(const unsigned*)swaddr(Bc, br, k0 + 8 + tig * 2);
            }
            #pragma unroll
            for (int mi = 0; mi < 2; mi++) {
                int ar = wm_ + mi * 16 + gid;
                unsigned a0 = *(const unsigned*)swaddr(Ac, ar,     k0 + tig * 2);
                unsigned a1 = *(const unsigned*)swaddr(Ac, ar + 8, k0 + tig * 2);
                unsigned a2 = *(const unsigned*)swaddr(Ac, ar,     k0 + 8 + tig * 2);
                unsigned a3 = *(const unsigned*)swaddr(Ac, ar + 8, k0 + 8 + tig * 2);
                #pragma unroll
                for (int ni = 0; ni < 4; ni++) {
                    asm volatile(
                        "mma.sync.aligned.m16n8k16.row.col.f32.bf16.bf16.f32 "
                        "{%0,%1,%2,%3}, {%4,%5,%6,%7}, {%8,%9}, {%0,%1,%2,%3};\n"
                        : "+f"(acc[mi][ni][0]), "+f"(acc[mi][ni][1]),
                          "+f"(acc[mi][ni][2]), "+f"(acc[mi][ni][3])
                        : "r"(a0), "r"(a1), "r"(a2), "r"(a3),
                          "r"(b0[ni]), "r"(b1[ni]));
                }
            }
        }
        __syncthreads();
    }

    #pragma unroll
    for (int mi = 0; mi < 2; mi++) {
        int row = bm + wm_ + mi * 16 + gid;
        #pragma unroll
        for (int ni = 0; ni < 4; ni++) {
            int col = bn + wn_ + ni * 8 + tig * 2;
            *(float2*)(g_gates + (size_t)row * 512 + col) =
                make_float2(acc[mi][ni][0], acc[mi][ni][1]);
            *(float2*)(g_gates + (size_t)(row + 8) * 512 + col) =
                make_float2(acc[mi][ni][2], acc[mi][ni][3]);
        }
    }
}

// ---------------------------------------------------------------------------
// LSTM elementwise update (also emits bf16 hi/lo of new h into A panel)
// ---------------------------------------------------------------------------
__global__ void lstm_update(int G) {
    int tid = blockIdx.x * blockDim.x + threadIdx.x;
    if (tid >= G * D) return;
    int row = tid / D, d = tid % D;
    const float* gr = g_gates + (size_t)row * 4 * D;
    float gi = gr[d]         + g_bias[d];
    float gf = gr[D + d]     + g_bias[D + d];
    float gg = gr[2 * D + d] + g_bias[2 * D + d];
    float go = gr[3 * D + d] + g_bias[3 * D + d];
    float c = sigf(gf) * g_c[tid] + sigf(gi) * tanhf(gg);
    float h = sigf(go) * tanhf(c);
    g_c[tid] = c;
    g_h[tid] = h;
    __nv_bfloat16 hh = __float2bfloat16(h);
    g_A[(size_t)row * 512 + d] = hh;
    g_A[(size_t)row * 512 + 256 + d] = __float2bfloat16(h - __bfloat162float(hh));
}

// ---------------------------------------------------------------------------
// final output: q_star = [h | r]
// ---------------------------------------------------------------------------
__global__ void assemble_kernel(float* __restrict__ out, int G) {
    int tid = blockIdx.x * blockDim.x + threadIdx.x;
    if (tid >= G * 2 * D) return;
    int row = tid / (2 * D), d = tid % (2 * D);
    out[tid] = (d < D) ? g_h[(size_t)row * D + d]
                       : g_r[(size_t)row * D + (d - D)];
}

// ---------------------------------------------------------------------------
extern "C" void kernel_launch(void* const* d_in, const int* in_sizes, int n_in,
                              void* d_out, int out_size) {
    const float* x    = (const float*)d_in[0];
    const float* W_ih = (const float*)d_in[1];
    const float* W_hh = (const float*)d_in[2];
    const float* b_ih = (const float*)d_in[3];
    const float* b_hh = (const float*)d_in[4];
    const void*  idx  = d_in[5];
    int N = in_sizes[5];
    int G = out_size / (2 * D);      // 4096
    float* out = (float*)d_out;

    int prep_total = 512 * 768;
    prep_kernel<<<(prep_total + 255) / 256, 256>>>(W_ih, W_hh, b_ih, b_hh, idx, N, G);
    init_state_kernel<<<(G * D + 255) / 256, 256>>>(G);
    segment_kernel<<<G, 256>>>(x);

    dim3 ggrid(G / 128, 512 / 64);
    for (int s = 1; s < 3; s++) {
        gates_gemm_mma<<<ggrid, 256>>>();
        lstm_update<<<(G * D + 255) / 256, 256>>>(G);
        segment_kernel<<<G, 256>>>(x);
    }
    assemble_kernel<<<(G * 2 * D + 255) / 256, 256>>>(out, G);
}